// round 1
// baseline (speedup 1.0000x reference)
#include <cuda_runtime.h>
#include <math.h>

// Problem constants (B=4, C=64, H=W=256)
#define BSZ 4
#define HDIM 256
#define WDIM 256
#define HW 65536

// ---------------- scratch (device globals; no allocation allowed) ----------------
__device__ float g_fre1[(size_t)BSZ * 64 * HW];
__device__ float g_spa1[(size_t)BSZ * 64 * HW];
__device__ float g_tmp [(size_t)BSZ * 64 * HW];   // 1x1 q intermediate, later t1
__device__ float g_q   [(size_t)BSZ * 64 * HW];
__device__ float g_fre2[(size_t)BSZ * 64 * HW];
__device__ float g_spa2[(size_t)BSZ * 64 * HW];
__device__ float g_kv0 [(size_t)BSZ * 128 * HW];  // 1x1 kv intermediate, later fuse
__device__ float g_kv  [(size_t)BSZ * 128 * HW];
// stats: G[4][8][8][8] at 0, nq[4][64] at 2048, nk[4][64] at 2304
__device__ float g_stats[2560];
__device__ float g_Meff[BSZ * 64 * 64];

// ---------------- small utility kernels ----------------
__global__ void zero_k(float* p, int n) {
    int i = blockIdx.x * 256 + threadIdx.x;
    if (i < n) p[i] = 0.f;
}

__device__ __forceinline__ float fix_nan(float x) {
    return isfinite(x) ? x : 1e-5f;
}

// ---------------- conv 3x3, pad 1, optional bias / sigmoid ----------------
// Block: 256 threads. Tile: 8 rows x 32 cols of output, 16 output channels.
// Input channels chunked by 16 through shared memory. Input may be a virtual
// concat of inA (channels [0,64)) and inB (channels [64,128)).
template <int CIN, bool SIG>
__global__ void conv3x3_k(const float* __restrict__ inA, const float* __restrict__ inB,
                          const float* __restrict__ Wt, const float* __restrict__ bias,
                          float* __restrict__ out, int coutTotal) {
    __shared__ float s_in[16][10][35];   // padded to 35 cols (bank-conflict-free)
    __shared__ float s_w[16][16][9];     // [ci][co_local][tap]

    const int groups = coutTotal >> 4;
    const int b     = blockIdx.z / groups;
    const int cout0 = (blockIdx.z % groups) << 4;
    const int x0 = blockIdx.x * 32;
    const int y0 = blockIdx.y * 8;

    const int t   = threadIdx.x;
    const int pg  = t & 63;          // pixel group 0..63
    const int cg  = t >> 6;          // cout group 0..3
    const int row = pg >> 3;         // 0..7
    const int xl0 = (pg & 7) << 2;   // 0,4,...,28
    const int col0 = cg << 2;        // 0,4,8,12

    float acc[4][4];
#pragma unroll
    for (int j = 0; j < 4; ++j)
#pragma unroll
        for (int p = 0; p < 4; ++p) acc[j][p] = 0.f;

    for (int ch0 = 0; ch0 < CIN; ch0 += 16) {
        // load input tile (16 ch x 10 x 34), zero-padded at image border
        for (int i = t; i < 16 * 10 * 34; i += 256) {
            int ci  = i / 340;
            int rem = i - ci * 340;
            int r = rem / 34, c = rem - r * 34;
            int gy = y0 + r - 1, gx = x0 + c - 1;
            int cig = ch0 + ci;
            const float* src = (cig < 64) ? inA : inB;
            int ch = (cig < 64) ? cig : (cig - 64);
            float v = 0.f;
            if (gy >= 0 && gy < HDIM && gx >= 0 && gx < WDIM)
                v = src[((size_t)b * 64 + ch) * HW + gy * WDIM + gx];
            s_in[ci][r][c] = v;
        }
        // load weights (16 ci x 16 co x 9)
        for (int i = t; i < 16 * 16 * 9; i += 256) {
            int tap = i % 9;
            int col = (i / 9) & 15;
            int ci  = i / 144;
            s_w[ci][col][tap] = Wt[((size_t)(cout0 + col) * CIN + (ch0 + ci)) * 9 + tap];
        }
        __syncthreads();

        for (int ci = 0; ci < 16; ++ci) {
            float v[3][6];
#pragma unroll
            for (int ky = 0; ky < 3; ++ky)
#pragma unroll
                for (int c = 0; c < 6; ++c) v[ky][c] = s_in[ci][row + ky][xl0 + c];
#pragma unroll
            for (int j = 0; j < 4; ++j) {
                const float w0 = s_w[ci][col0 + j][0];
                const float w1 = s_w[ci][col0 + j][1];
                const float w2 = s_w[ci][col0 + j][2];
                const float w3 = s_w[ci][col0 + j][3];
                const float w4 = s_w[ci][col0 + j][4];
                const float w5 = s_w[ci][col0 + j][5];
                const float w6 = s_w[ci][col0 + j][6];
                const float w7 = s_w[ci][col0 + j][7];
                const float w8 = s_w[ci][col0 + j][8];
#pragma unroll
                for (int p = 0; p < 4; ++p) {
                    acc[j][p] += w0 * v[0][p] + w1 * v[0][p + 1] + w2 * v[0][p + 2]
                               + w3 * v[1][p] + w4 * v[1][p + 1] + w5 * v[1][p + 2]
                               + w6 * v[2][p] + w7 * v[2][p + 1] + w8 * v[2][p + 2];
                }
            }
        }
        __syncthreads();
    }

#pragma unroll
    for (int j = 0; j < 4; ++j) {
        int co = cout0 + col0 + j;
        float bv = bias ? bias[co] : 0.f;
        float4 r;
        r.x = acc[j][0] + bv;
        r.y = acc[j][1] + bv;
        r.z = acc[j][2] + bv;
        r.w = acc[j][3] + bv;
        if (SIG) {
            r.x = 1.f / (1.f + expf(-r.x));
            r.y = 1.f / (1.f + expf(-r.y));
            r.z = 1.f / (1.f + expf(-r.z));
            r.w = 1.f / (1.f + expf(-r.w));
        }
        *(float4*)&out[((size_t)b * coutTotal + co) * HW + (size_t)(y0 + row) * WDIM + x0 + xl0] = r;
    }
}

// ---------------- conv 1x1 (per-pixel GEMM), cin=64, 64 couts per grid.y ----------------
// Block: 256 threads. Thread = 4 pixels x 8 couts. Weights staged in smem.
// Supports per-batch weights (w_bs) and residual add.
__global__ void conv1x1_k(const float* __restrict__ in, int in_cs, int in_off,
                          const float* __restrict__ W, int w_bs,
                          const float* __restrict__ resid,
                          float* __restrict__ out, int out_cs) {
    __shared__ float s_w[64 * 64];  // [ci][co_local]
    const int b   = blockIdx.z;
    const int co0 = blockIdx.y * 64;
    const int t   = threadIdx.x;
    const int pg  = t & 31;
    const int cg  = t >> 5;        // 0..7
    const int p   = blockIdx.x * 128 + pg * 4;

    const float* wb = W + (size_t)b * w_bs;
    for (int i = t; i < 64 * 64; i += 256) {
        int ci = i >> 6, col = i & 63;
        s_w[ci * 64 + col] = wb[(size_t)(co0 + col) * 64 + ci];
    }
    __syncthreads();

    float acc[8][4];
#pragma unroll
    for (int j = 0; j < 8; ++j)
#pragma unroll
        for (int q = 0; q < 4; ++q) acc[j][q] = 0.f;

    const float* ip = in + ((size_t)b * in_cs + in_off) * HW + p;
#pragma unroll 4
    for (int ci = 0; ci < 64; ++ci) {
        float4 xv = *(const float4*)(ip + (size_t)ci * HW);
#pragma unroll
        for (int j = 0; j < 8; ++j) {
            float w = s_w[ci * 64 + cg * 8 + j];
            acc[j][0] += w * xv.x;
            acc[j][1] += w * xv.y;
            acc[j][2] += w * xv.z;
            acc[j][3] += w * xv.w;
        }
    }

#pragma unroll
    for (int j = 0; j < 8; ++j) {
        int co = co0 + cg * 8 + j;
        size_t oidx = ((size_t)b * out_cs + co) * HW + p;
        float4 r = make_float4(acc[j][0], acc[j][1], acc[j][2], acc[j][3]);
        if (resid) {
            float4 rv = *(const float4*)(resid + oidx);
            r.x += rv.x; r.y += rv.y; r.z += rv.z; r.w += rv.w;
        }
        *(float4*)(out + oidx) = r;
    }
}

// ---------------- depthwise 3x3, pad 1, no bias ----------------
__global__ void dw3x3_k(const float* __restrict__ in, const float* __restrict__ wt,
                        float* __restrict__ out, int C) {
    const int x = blockIdx.x * 32 + (threadIdx.x & 31);
    const int y = blockIdx.y * 8 + (threadIdx.x >> 5);
    const int zc = blockIdx.z;       // b*C + c
    const int c = zc % C;
    const float* ip = in + (size_t)zc * HW;
    float w[9];
#pragma unroll
    for (int i = 0; i < 9; ++i) w[i] = __ldg(&wt[c * 9 + i]);
    float s = 0.f;
#pragma unroll
    for (int ky = 0; ky < 3; ++ky) {
        int yy = y + ky - 1;
        if (yy < 0 || yy >= HDIM) continue;
#pragma unroll
        for (int kx = 0; kx < 3; ++kx) {
            int xx = x + kx - 1;
            if (xx < 0 || xx >= WDIM) continue;
            s += w[ky * 3 + kx] * __ldg(ip + yy * WDIM + xx);
        }
    }
    out[(size_t)zc * HW + y * WDIM + x] = s;
}

// ---------------- Gram matrix + channel norms, per (b, head) ----------------
// grid: (16 slices, 8 heads, 4 batch), block 256.
__global__ void gramnorm_k(const float* __restrict__ q, int qcs,
                           const float* __restrict__ k, int kcs,
                           float* __restrict__ G, float* __restrict__ nq,
                           float* __restrict__ nk) {
    const int b = blockIdx.z, h = blockIdx.y;
    const int p0 = blockIdx.x * 4096 + threadIdx.x;
    const float* qb = q + ((size_t)b * qcs + h * 8) * HW;
    const float* kb = k + ((size_t)b * kcs + h * 8) * HW;

    float acc[80];
#pragma unroll
    for (int i = 0; i < 80; ++i) acc[i] = 0.f;

    for (int it = 0; it < 16; ++it) {
        int p = p0 + it * 256;
        float qv[8], kv[8];
#pragma unroll
        for (int c = 0; c < 8; ++c) {
            qv[c] = qb[(size_t)c * HW + p];
            kv[c] = kb[(size_t)c * HW + p];
        }
#pragma unroll
        for (int c = 0; c < 8; ++c) {
            acc[64 + c] += qv[c] * qv[c];
            acc[72 + c] += kv[c] * kv[c];
#pragma unroll
            for (int d = 0; d < 8; ++d) acc[c * 8 + d] += qv[c] * kv[d];
        }
    }

    __shared__ float red[80][8];
    const int lane = threadIdx.x & 31, warp = threadIdx.x >> 5;
#pragma unroll
    for (int i = 0; i < 80; ++i) {
        float v = acc[i];
        v += __shfl_down_sync(0xffffffffu, v, 16);
        v += __shfl_down_sync(0xffffffffu, v, 8);
        v += __shfl_down_sync(0xffffffffu, v, 4);
        v += __shfl_down_sync(0xffffffffu, v, 2);
        v += __shfl_down_sync(0xffffffffu, v, 1);
        if (lane == 0) red[i][warp] = v;
    }
    __syncthreads();
    if (threadIdx.x < 80) {
        float s = 0.f;
#pragma unroll
        for (int w = 0; w < 8; ++w) s += red[threadIdx.x][w];
        int i = threadIdx.x;
        if (i < 64)
            atomicAdd(&G[(((size_t)b * 8 + h) * 8 + (i >> 3)) * 8 + (i & 7)], s);
        else if (i < 72)
            atomicAdd(&nq[b * 64 + h * 8 + (i - 64)], s);
        else
            atomicAdd(&nk[b * 64 + h * 8 + (i - 72)], s);
    }
}

// ---------------- softmax + fold proj: Meff[b] = Wproj @ blockdiag(attn) ----------------
// grid: 4 blocks (batch), 64 threads.
__global__ void softmax_meff_k(const float* __restrict__ temp, const float* __restrict__ Wproj,
                               const float* __restrict__ G, const float* __restrict__ nq,
                               const float* __restrict__ nk, float* __restrict__ Meff) {
    const int b = blockIdx.x;
    const int t = threadIdx.x;   // 0..63
    __shared__ float attn[8][8][8];  // [head][c][d]
    {
        int h = t >> 3, c = t & 7;
        float nqc = fmaxf(sqrtf(nq[b * 64 + h * 8 + c]), 1e-12f);
        float row[8];
        float m = -1e30f;
#pragma unroll
        for (int d = 0; d < 8; ++d) {
            float nkd = fmaxf(sqrtf(nk[b * 64 + h * 8 + d]), 1e-12f);
            row[d] = temp[h] * G[(((size_t)b * 8 + h) * 8 + c) * 8 + d] / (nqc * nkd);
            m = fmaxf(m, row[d]);
        }
        float sum = 0.f;
#pragma unroll
        for (int d = 0; d < 8; ++d) { row[d] = expf(row[d] - m); sum += row[d]; }
        float inv = 1.f / sum;
#pragma unroll
        for (int d = 0; d < 8; ++d) attn[h][c][d] = row[d] * inv;
    }
    __syncthreads();
    const int o = t;
    for (int dg = 0; dg < 64; ++dg) {
        int hh = dg >> 3, j = dg & 7;
        float s = 0.f;
#pragma unroll
        for (int i = 0; i < 8; ++i) s += Wproj[o * 64 + hh * 8 + i] * attn[hh][i][j];
        Meff[((size_t)b * 64 + o) * 64 + dg] = s;
    }
}

// ---------------- final gate: res = fre2*fuse[:64] + spa2*fuse[64:], nan_to_num ----------------
__global__ void final_k(const float* __restrict__ f, const float* __restrict__ s,
                        const float* __restrict__ fuse, float* __restrict__ out) {
    size_t i4 = (size_t)blockIdx.x * 256 + threadIdx.x;
    size_t e = i4 * 4;
    int bc = (int)(e / HW);
    int p  = (int)(e % HW);
    int b = bc >> 6, c = bc & 63;
    float4 fv = *(const float4*)(f + e);
    float4 sv = *(const float4*)(s + e);
    float4 fa = *(const float4*)(fuse + ((size_t)(b * 128 + c)) * HW + p);
    float4 sa = *(const float4*)(fuse + ((size_t)(b * 128 + 64 + c)) * HW + p);
    float4 r;
    r.x = fix_nan(fv.x * fa.x + sv.x * sa.x);
    r.y = fix_nan(fv.y * fa.y + sv.y * sa.y);
    r.z = fix_nan(fv.z * fa.z + sv.z * sa.z);
    r.w = fix_nan(fv.w * fa.w + sv.w * sa.w);
    *(float4*)(out + e) = r;
}

// ---------------- host orchestration ----------------
extern "C" void kernel_launch(void* const* d_in, const int* in_sizes, int n_in,
                              void* d_out, int out_size) {
    const float* spa    = (const float*)d_in[0];
    const float* fre    = (const float*)d_in[1];
    const float* W_fre  = (const float*)d_in[2];
    const float* b_fre  = (const float*)d_in[3];
    const float* W_spa  = (const float*)d_in[4];
    const float* b_spa  = (const float*)d_in[5];
    const float* temp   = (const float*)d_in[6];
    const float* Wq     = (const float*)d_in[7];
    const float* Wq_dw  = (const float*)d_in[8];
    const float* Wkv    = (const float*)d_in[9];
    const float* Wkv_dw = (const float*)d_in[10];
    const float* Wproj  = (const float*)d_in[11];
    const float* Wf1    = (const float*)d_in[12];
    const float* bf1    = (const float*)d_in[13];
    const float* Wf2    = (const float*)d_in[14];
    const float* bf2    = (const float*)d_in[15];
    float* out = (float*)d_out;

    float *pfre1, *pspa1, *ptmp, *pq, *pfre2, *pspa2, *pkv0, *pkv, *pstats, *pmeff;
    cudaGetSymbolAddress((void**)&pfre1, g_fre1);
    cudaGetSymbolAddress((void**)&pspa1, g_spa1);
    cudaGetSymbolAddress((void**)&ptmp,  g_tmp);
    cudaGetSymbolAddress((void**)&pq,    g_q);
    cudaGetSymbolAddress((void**)&pfre2, g_fre2);
    cudaGetSymbolAddress((void**)&pspa2, g_spa2);
    cudaGetSymbolAddress((void**)&pkv0,  g_kv0);
    cudaGetSymbolAddress((void**)&pkv,   g_kv);
    cudaGetSymbolAddress((void**)&pstats, g_stats);
    cudaGetSymbolAddress((void**)&pmeff, g_Meff);
    float* pG  = pstats;
    float* pnq = pstats + 2048;
    float* pnk = pstats + 2304;

    const dim3 blk(256);
    const dim3 g3(8, 32, BSZ * 4);          // conv3x3 64->64
    const dim3 g3f2(8, 32, BSZ * 8);        // conv3x3 64->128
    const dim3 g1(512, 1, BSZ);             // conv1x1 64 couts
    const dim3 g1kv(512, 2, BSZ);           // conv1x1 128 couts
    const dim3 gdw64(8, 32, BSZ * 64);
    const dim3 gdw128(8, 32, BSZ * 128);
    const dim3 ggram(16, 8, BSZ);

    // 1) fre1 = conv3x3(fre, W_fre) + b_fre ; spa1 = conv3x3(spa, W_spa) + b_spa
    conv3x3_k<64, false><<<g3, blk>>>(fre, fre, W_fre, b_fre, pfre1, 64);
    conv3x3_k<64, false><<<g3, blk>>>(spa, spa, W_spa, b_spa, pspa1, 64);

    // ===== attention 1: q from fre1, kv from spa1, residual fre1 -> fre2 =====
    conv1x1_k<<<g1kv, blk>>>(pspa1, 64, 0, Wkv, 0, nullptr, pkv0, 128);
    dw3x3_k<<<gdw128, blk>>>(pkv0, Wkv_dw, pkv, 128);
    conv1x1_k<<<g1, blk>>>(pfre1, 64, 0, Wq, 0, nullptr, ptmp, 64);
    dw3x3_k<<<gdw64, blk>>>(ptmp, Wq_dw, pq, 64);
    zero_k<<<10, 256>>>(pstats, 2560);
    gramnorm_k<<<ggram, blk>>>(pq, 64, pkv, 128, pG, pnq, pnk);
    softmax_meff_k<<<BSZ, 64>>>(temp, Wproj, pG, pnq, pnk, pmeff);
    conv1x1_k<<<g1, blk>>>(pkv, 128, 64, pmeff, 64 * 64, pfre1, pfre2, 64);

    // ===== attention 2: q from spa1, kv from fre2, residual spa1 -> spa2 =====
    conv1x1_k<<<g1kv, blk>>>(pfre2, 64, 0, Wkv, 0, nullptr, pkv0, 128);
    dw3x3_k<<<gdw128, blk>>>(pkv0, Wkv_dw, pkv, 128);
    conv1x1_k<<<g1, blk>>>(pspa1, 64, 0, Wq, 0, nullptr, ptmp, 64);
    dw3x3_k<<<gdw64, blk>>>(ptmp, Wq_dw, pq, 64);
    zero_k<<<10, 256>>>(pstats, 2560);
    gramnorm_k<<<ggram, blk>>>(pq, 64, pkv, 128, pG, pnq, pnk);
    softmax_meff_k<<<BSZ, 64>>>(temp, Wproj, pG, pnq, pnk, pmeff);
    conv1x1_k<<<g1, blk>>>(pkv, 128, 64, pmeff, 64 * 64, pspa1, pspa2, 64);

    // ===== fuse path =====
    // t1 = conv3x3(concat(fre2, spa2), Wf1) + bf1   (128 -> 64)
    conv3x3_k<128, false><<<g3, blk>>>(pfre2, pspa2, Wf1, bf1, ptmp, 64);
    // fuse = sigmoid(conv3x3(t1, Wf2) + bf2)        (64 -> 128)
    conv3x3_k<64, true><<<g3f2, blk>>>(ptmp, ptmp, Wf2, bf2, pkv0, 128);
    // res = fre2*fuse[:64] + spa2*fuse[64:], nan_to_num
    final_k<<<16384, 256>>>(pfre2, pspa2, pkv0, out);
}

// round 2
// speedup vs baseline: 1.0617x; 1.0617x over previous
#include <cuda_runtime.h>
#include <math.h>

// Problem constants (B=4, C=64, H=W=256)
#define BSZ 4
#define HDIM 256
#define WDIM 256
#define HW 65536

typedef unsigned long long ull;

// ---------------- scratch (device globals; no allocation allowed) ----------------
__device__ float g_fre1[(size_t)BSZ * 64 * HW];
__device__ float g_spa1[(size_t)BSZ * 64 * HW];
__device__ float g_tmp [(size_t)BSZ * 64 * HW];   // 1x1 q intermediate, later t1
__device__ float g_q   [(size_t)BSZ * 64 * HW];
__device__ float g_fre2[(size_t)BSZ * 64 * HW];
__device__ float g_spa2[(size_t)BSZ * 64 * HW];
__device__ float g_kv0 [(size_t)BSZ * 128 * HW];  // 1x1 kv intermediate, later fuse
__device__ float g_kv  [(size_t)BSZ * 128 * HW];
// stats: G[4][8][8][8] at 0, nq[4][64] at 2048, nk[4][64] at 2304
__device__ float g_stats[2560];
__device__ float g_Meff[BSZ * 64 * 64];

// ---------------- packed f32x2 helpers (FFMA2 — ptxas won't emit from C++) ----------------
__device__ __forceinline__ ull ffma2(ull a, ull b, ull c) {
    ull d;
    asm("fma.rn.f32x2 %0, %1, %2, %3;" : "=l"(d) : "l"(a), "l"(b), "l"(c));
    return d;
}
__device__ __forceinline__ ull packf2(float x, float y) {
    ull u; asm("mov.b64 %0, {%1, %2};" : "=l"(u) : "f"(x), "f"(y)); return u;
}
__device__ __forceinline__ float2 unpackf2(ull u) {
    float2 v; asm("mov.b64 {%0, %1}, %2;" : "=f"(v.x), "=f"(v.y) : "l"(u)); return v;
}

// ---------------- small utility kernels ----------------
__global__ void zero_k(float* p, int n) {
    int i = blockIdx.x * 256 + threadIdx.x;
    if (i < n) p[i] = 0.f;
}

__device__ __forceinline__ float fix_nan(float x) {
    return isfinite(x) ? x : 1e-5f;
}

// ---------------- conv 3x3, pad 1, optional bias / sigmoid, FFMA2 ----------------
// Block: 256 threads. Tile: 8 rows x 32 cols of output, 16 output channels.
// Input channels processed in pairs (packed float2); chunked by 16 through smem.
template <int CIN, bool SIG>
__global__ void __launch_bounds__(256)
conv3x3_k(const float* __restrict__ inA, const float* __restrict__ inB,
          const float* __restrict__ Wt, const float* __restrict__ bias,
          float* __restrict__ out, int coutTotal) {
    __shared__ float2 s_in[8][10][36];   // [ci2][row][col]; 36-col pad = 16B-aligned rows
    __shared__ float2 s_w[8][16][10];    // [ci2][co_local][tap(9, pad 10)]

    const int groups = coutTotal >> 4;
    const int b     = blockIdx.z / groups;
    const int cout0 = (blockIdx.z % groups) << 4;
    const int x0 = blockIdx.x * 32;
    const int y0 = blockIdx.y * 8;

    const int t   = threadIdx.x;
    const int pg  = t & 63;          // pixel group 0..63
    const int cg  = t >> 6;          // cout group 0..3
    const int row = pg >> 3;         // 0..7
    const int xl0 = (pg & 7) << 2;   // 0,4,...,28
    const int col0 = cg << 2;        // 0,4,8,12

    ull acc[4][4];
#pragma unroll
    for (int j = 0; j < 4; ++j)
#pragma unroll
        for (int p = 0; p < 4; ++p) acc[j][p] = 0ull;

    for (int ch0 = 0; ch0 < CIN; ch0 += 16) {
        // stage input tile (16 ch x 10 x 34), interleaved into channel pairs
        for (int i = t; i < 16 * 10 * 34; i += 256) {
            int ci  = i / 340;
            int rem = i - ci * 340;
            int r = rem / 34, c = rem - r * 34;
            int gy = y0 + r - 1, gx = x0 + c - 1;
            int cig = ch0 + ci;
            const float* src = (cig < 64) ? inA : inB;
            int ch = (cig < 64) ? cig : (cig - 64);
            float v = 0.f;
            if (gy >= 0 && gy < HDIM && gx >= 0 && gx < WDIM)
                v = src[((size_t)b * 64 + ch) * HW + gy * WDIM + gx];
            ((float*)&s_in[ci >> 1][r][c])[ci & 1] = v;
        }
        // stage weights as channel pairs: 8 ci2 x 16 co x 9 taps
        for (int i = t; i < 8 * 16 * 9; i += 256) {
            int tap = i % 9;
            int rest = i / 9;
            int col = rest & 15;
            int ci2 = rest >> 4;
            int cib = ch0 + ci2 * 2;
            float wx = Wt[((size_t)(cout0 + col) * CIN + cib) * 9 + tap];
            float wy = Wt[((size_t)(cout0 + col) * CIN + cib + 1) * 9 + tap];
            s_w[ci2][col][tap] = make_float2(wx, wy);
        }
        __syncthreads();

#pragma unroll
        for (int ci2 = 0; ci2 < 8; ++ci2) {
            ull v[3][6];
#pragma unroll
            for (int ky = 0; ky < 3; ++ky) {
                const ulonglong2* vp = (const ulonglong2*)&s_in[ci2][row + ky][xl0];
                ulonglong2 q0 = vp[0], q1 = vp[1], q2 = vp[2];
                v[ky][0] = q0.x; v[ky][1] = q0.y;
                v[ky][2] = q1.x; v[ky][3] = q1.y;
                v[ky][4] = q2.x; v[ky][5] = q2.y;
            }
#pragma unroll
            for (int j = 0; j < 4; ++j) {
                const ull* wr = (const ull*)&s_w[ci2][col0 + j][0];
                ull w[9];
#pragma unroll
                for (int tap = 0; tap < 9; ++tap) w[tap] = wr[tap];
#pragma unroll
                for (int ky = 0; ky < 3; ++ky)
#pragma unroll
                    for (int kx = 0; kx < 3; ++kx) {
#pragma unroll
                        for (int p = 0; p < 4; ++p)
                            acc[j][p] = ffma2(w[ky * 3 + kx], v[ky][p + kx], acc[j][p]);
                    }
            }
        }
        __syncthreads();
    }

#pragma unroll
    for (int j = 0; j < 4; ++j) {
        int co = cout0 + col0 + j;
        float bv = bias ? bias[co] : 0.f;
        float4 r;
        float2 a0 = unpackf2(acc[j][0]);
        float2 a1 = unpackf2(acc[j][1]);
        float2 a2 = unpackf2(acc[j][2]);
        float2 a3 = unpackf2(acc[j][3]);
        r.x = a0.x + a0.y + bv;
        r.y = a1.x + a1.y + bv;
        r.z = a2.x + a2.y + bv;
        r.w = a3.x + a3.y + bv;
        if (SIG) {
            r.x = 1.f / (1.f + expf(-r.x));
            r.y = 1.f / (1.f + expf(-r.y));
            r.z = 1.f / (1.f + expf(-r.z));
            r.w = 1.f / (1.f + expf(-r.w));
        }
        *(float4*)&out[((size_t)b * coutTotal + co) * HW + (size_t)(y0 + row) * WDIM + x0 + xl0] = r;
    }
}

// ---------------- conv 1x1 (per-pixel GEMM), cin=64, 64 couts per grid.y, FFMA2 ----------------
// Block: 256 threads. Thread = 4 pixels (2 packed pairs) x 8 couts.
// Weights staged duplicated (w,w) in smem. Per-batch weights (w_bs) + residual supported.
__global__ void __launch_bounds__(256)
conv1x1_k(const float* __restrict__ in, int in_cs, int in_off,
          const float* __restrict__ W, int w_bs,
          const float* __restrict__ resid,
          float* __restrict__ out, int out_cs) {
    __shared__ ull s_w[64 * 64];  // [ci][co_local] as (w,w)
    const int b   = blockIdx.z;
    const int co0 = blockIdx.y * 64;
    const int t   = threadIdx.x;
    const int pg  = t & 31;
    const int cg  = t >> 5;        // 0..7
    const int p   = blockIdx.x * 128 + pg * 4;

    const float* wb = W + (size_t)b * w_bs;
    for (int i = t; i < 64 * 64; i += 256) {
        int ci = i >> 6, col = i & 63;
        float w = wb[(size_t)(co0 + col) * 64 + ci];
        s_w[i] = packf2(w, w);
    }
    __syncthreads();

    ull acc[8][2];
#pragma unroll
    for (int j = 0; j < 8; ++j) { acc[j][0] = 0ull; acc[j][1] = 0ull; }

    const float* ip = in + ((size_t)b * in_cs + in_off) * HW + p;
#pragma unroll 4
    for (int ci = 0; ci < 64; ++ci) {
        ulonglong2 X = *(const ulonglong2*)(ip + (size_t)ci * HW);
        const ull* wr = &s_w[ci * 64 + cg * 8];
#pragma unroll
        for (int j = 0; j < 8; ++j) {
            acc[j][0] = ffma2(wr[j], X.x, acc[j][0]);
            acc[j][1] = ffma2(wr[j], X.y, acc[j][1]);
        }
    }

#pragma unroll
    for (int j = 0; j < 8; ++j) {
        int co = co0 + cg * 8 + j;
        size_t oidx = ((size_t)b * out_cs + co) * HW + p;
        float2 lo = unpackf2(acc[j][0]);
        float2 hi = unpackf2(acc[j][1]);
        float4 r = make_float4(lo.x, lo.y, hi.x, hi.y);
        if (resid) {
            float4 rv = *(const float4*)(resid + oidx);
            r.x += rv.x; r.y += rv.y; r.z += rv.z; r.w += rv.w;
        }
        *(float4*)(out + oidx) = r;
    }
}

// ---------------- depthwise 3x3, pad 1, no bias; 4 px/thread, hoisted predicates ----------------
// grid: (4, 16, B*C), block 256. Tile: 64 px wide x 16 rows.
__global__ void dw3x3_k(const float* __restrict__ in, const float* __restrict__ wt,
                        float* __restrict__ out, int C) {
    const int t = threadIdx.x;
    const int x0 = blockIdx.x * 64 + (t & 15) * 4;
    const int y  = blockIdx.y * 16 + (t >> 4);
    const int zc = blockIdx.z;       // b*C + c
    const int c = zc % C;
    const float* ip = in + (size_t)zc * HW;

    float w[9];
#pragma unroll
    for (int i = 0; i < 9; ++i) w[i] = __ldg(&wt[c * 9 + i]);

    float acc[4] = {0.f, 0.f, 0.f, 0.f};
    const bool hasL = (x0 > 0), hasR = (x0 < WDIM - 4);
#pragma unroll
    for (int ky = 0; ky < 3; ++ky) {
        int yy = y + ky - 1;
        if (yy < 0 || yy >= HDIM) continue;
        const float* rp = ip + yy * WDIM + x0;
        float4 m = *(const float4*)rp;
        float v[6];
        v[0] = hasL ? __ldg(rp - 1) : 0.f;
        v[1] = m.x; v[2] = m.y; v[3] = m.z; v[4] = m.w;
        v[5] = hasR ? __ldg(rp + 4) : 0.f;
#pragma unroll
        for (int kx = 0; kx < 3; ++kx)
#pragma unroll
            for (int p = 0; p < 4; ++p)
                acc[p] += w[ky * 3 + kx] * v[kx + p];
    }
    *(float4*)&out[(size_t)zc * HW + y * WDIM + x0] =
        make_float4(acc[0], acc[1], acc[2], acc[3]);
}

// ---------------- Gram matrix + channel norms, per (b, head) ----------------
// grid: (16 slices, 8 heads, 4 batch), block 256.
__global__ void gramnorm_k(const float* __restrict__ q, int qcs,
                           const float* __restrict__ k, int kcs,
                           float* __restrict__ G, float* __restrict__ nq,
                           float* __restrict__ nk) {
    const int b = blockIdx.z, h = blockIdx.y;
    const int p0 = blockIdx.x * 4096 + threadIdx.x;
    const float* qb = q + ((size_t)b * qcs + h * 8) * HW;
    const float* kb = k + ((size_t)b * kcs + h * 8) * HW;

    float acc[80];
#pragma unroll
    for (int i = 0; i < 80; ++i) acc[i] = 0.f;

    for (int it = 0; it < 16; ++it) {
        int p = p0 + it * 256;
        float qv[8], kv[8];
#pragma unroll
        for (int c = 0; c < 8; ++c) {
            qv[c] = qb[(size_t)c * HW + p];
            kv[c] = kb[(size_t)c * HW + p];
        }
#pragma unroll
        for (int c = 0; c < 8; ++c) {
            acc[64 + c] += qv[c] * qv[c];
            acc[72 + c] += kv[c] * kv[c];
#pragma unroll
            for (int d = 0; d < 8; ++d) acc[c * 8 + d] += qv[c] * kv[d];
        }
    }

    __shared__ float red[80][8];
    const int lane = threadIdx.x & 31, warp = threadIdx.x >> 5;
#pragma unroll
    for (int i = 0; i < 80; ++i) {
        float v = acc[i];
        v += __shfl_down_sync(0xffffffffu, v, 16);
        v += __shfl_down_sync(0xffffffffu, v, 8);
        v += __shfl_down_sync(0xffffffffu, v, 4);
        v += __shfl_down_sync(0xffffffffu, v, 2);
        v += __shfl_down_sync(0xffffffffu, v, 1);
        if (lane == 0) red[i][warp] = v;
    }
    __syncthreads();
    if (threadIdx.x < 80) {
        float s = 0.f;
#pragma unroll
        for (int w = 0; w < 8; ++w) s += red[threadIdx.x][w];
        int i = threadIdx.x;
        if (i < 64)
            atomicAdd(&G[(((size_t)b * 8 + h) * 8 + (i >> 3)) * 8 + (i & 7)], s);
        else if (i < 72)
            atomicAdd(&nq[b * 64 + h * 8 + (i - 64)], s);
        else
            atomicAdd(&nk[b * 64 + h * 8 + (i - 72)], s);
    }
}

// ---------------- softmax + fold proj: Meff[b] = Wproj @ blockdiag(attn) ----------------
__global__ void softmax_meff_k(const float* __restrict__ temp, const float* __restrict__ Wproj,
                               const float* __restrict__ G, const float* __restrict__ nq,
                               const float* __restrict__ nk, float* __restrict__ Meff) {
    const int b = blockIdx.x;
    const int t = threadIdx.x;   // 0..63
    __shared__ float attn[8][8][8];  // [head][c][d]
    {
        int h = t >> 3, c = t & 7;
        float nqc = fmaxf(sqrtf(nq[b * 64 + h * 8 + c]), 1e-12f);
        float row[8];
        float m = -1e30f;
#pragma unroll
        for (int d = 0; d < 8; ++d) {
            float nkd = fmaxf(sqrtf(nk[b * 64 + h * 8 + d]), 1e-12f);
            row[d] = temp[h] * G[(((size_t)b * 8 + h) * 8 + c) * 8 + d] / (nqc * nkd);
            m = fmaxf(m, row[d]);
        }
        float sum = 0.f;
#pragma unroll
        for (int d = 0; d < 8; ++d) { row[d] = expf(row[d] - m); sum += row[d]; }
        float inv = 1.f / sum;
#pragma unroll
        for (int d = 0; d < 8; ++d) attn[h][c][d] = row[d] * inv;
    }
    __syncthreads();
    const int o = t;
    for (int dg = 0; dg < 64; ++dg) {
        int hh = dg >> 3, j = dg & 7;
        float s = 0.f;
#pragma unroll
        for (int i = 0; i < 8; ++i) s += Wproj[o * 64 + hh * 8 + i] * attn[hh][i][j];
        Meff[((size_t)b * 64 + o) * 64 + dg] = s;
    }
}

// ---------------- final gate: res = fre2*fuse[:64] + spa2*fuse[64:], nan_to_num ----------------
__global__ void final_k(const float* __restrict__ f, const float* __restrict__ s,
                        const float* __restrict__ fuse, float* __restrict__ out) {
    size_t i4 = (size_t)blockIdx.x * 256 + threadIdx.x;
    size_t e = i4 * 4;
    int bc = (int)(e / HW);
    int p  = (int)(e % HW);
    int b = bc >> 6, c = bc & 63;
    float4 fv = *(const float4*)(f + e);
    float4 sv = *(const float4*)(s + e);
    float4 fa = *(const float4*)(fuse + ((size_t)(b * 128 + c)) * HW + p);
    float4 sa = *(const float4*)(fuse + ((size_t)(b * 128 + 64 + c)) * HW + p);
    float4 r;
    r.x = fix_nan(fv.x * fa.x + sv.x * sa.x);
    r.y = fix_nan(fv.y * fa.y + sv.y * sa.y);
    r.z = fix_nan(fv.z * fa.z + sv.z * sa.z);
    r.w = fix_nan(fv.w * fa.w + sv.w * sa.w);
    *(float4*)(out + e) = r;
}

// ---------------- host orchestration ----------------
extern "C" void kernel_launch(void* const* d_in, const int* in_sizes, int n_in,
                              void* d_out, int out_size) {
    const float* spa    = (const float*)d_in[0];
    const float* fre    = (const float*)d_in[1];
    const float* W_fre  = (const float*)d_in[2];
    const float* b_fre  = (const float*)d_in[3];
    const float* W_spa  = (const float*)d_in[4];
    const float* b_spa  = (const float*)d_in[5];
    const float* temp   = (const float*)d_in[6];
    const float* Wq     = (const float*)d_in[7];
    const float* Wq_dw  = (const float*)d_in[8];
    const float* Wkv    = (const float*)d_in[9];
    const float* Wkv_dw = (const float*)d_in[10];
    const float* Wproj  = (const float*)d_in[11];
    const float* Wf1    = (const float*)d_in[12];
    const float* bf1    = (const float*)d_in[13];
    const float* Wf2    = (const float*)d_in[14];
    const float* bf2    = (const float*)d_in[15];
    float* out = (float*)d_out;

    float *pfre1, *pspa1, *ptmp, *pq, *pfre2, *pspa2, *pkv0, *pkv, *pstats, *pmeff;
    cudaGetSymbolAddress((void**)&pfre1, g_fre1);
    cudaGetSymbolAddress((void**)&pspa1, g_spa1);
    cudaGetSymbolAddress((void**)&ptmp,  g_tmp);
    cudaGetSymbolAddress((void**)&pq,    g_q);
    cudaGetSymbolAddress((void**)&pfre2, g_fre2);
    cudaGetSymbolAddress((void**)&pspa2, g_spa2);
    cudaGetSymbolAddress((void**)&pkv0,  g_kv0);
    cudaGetSymbolAddress((void**)&pkv,   g_kv);
    cudaGetSymbolAddress((void**)&pstats, g_stats);
    cudaGetSymbolAddress((void**)&pmeff, g_Meff);
    float* pG  = pstats;
    float* pnq = pstats + 2048;
    float* pnk = pstats + 2304;

    const dim3 blk(256);
    const dim3 g3(8, 32, BSZ * 4);          // conv3x3 64->64
    const dim3 g3f2(8, 32, BSZ * 8);        // conv3x3 64->128
    const dim3 g1(512, 1, BSZ);             // conv1x1 64 couts
    const dim3 g1kv(512, 2, BSZ);           // conv1x1 128 couts
    const dim3 gdw64(4, 16, BSZ * 64);
    const dim3 gdw128(4, 16, BSZ * 128);
    const dim3 ggram(16, 8, BSZ);

    // 1) fre1 = conv3x3(fre, W_fre) + b_fre ; spa1 = conv3x3(spa, W_spa) + b_spa
    conv3x3_k<64, false><<<g3, blk>>>(fre, fre, W_fre, b_fre, pfre1, 64);
    conv3x3_k<64, false><<<g3, blk>>>(spa, spa, W_spa, b_spa, pspa1, 64);

    // ===== attention 1: q from fre1, kv from spa1, residual fre1 -> fre2 =====
    conv1x1_k<<<g1kv, blk>>>(pspa1, 64, 0, Wkv, 0, nullptr, pkv0, 128);
    dw3x3_k<<<gdw128, blk>>>(pkv0, Wkv_dw, pkv, 128);
    conv1x1_k<<<g1, blk>>>(pfre1, 64, 0, Wq, 0, nullptr, ptmp, 64);
    dw3x3_k<<<gdw64, blk>>>(ptmp, Wq_dw, pq, 64);
    zero_k<<<10, 256>>>(pstats, 2560);
    gramnorm_k<<<ggram, blk>>>(pq, 64, pkv, 128, pG, pnq, pnk);
    softmax_meff_k<<<BSZ, 64>>>(temp, Wproj, pG, pnq, pnk, pmeff);
    conv1x1_k<<<g1, blk>>>(pkv, 128, 64, pmeff, 64 * 64, pfre1, pfre2, 64);

    // ===== attention 2: q from spa1, kv from fre2, residual spa1 -> spa2 =====
    conv1x1_k<<<g1kv, blk>>>(pfre2, 64, 0, Wkv, 0, nullptr, pkv0, 128);
    dw3x3_k<<<gdw128, blk>>>(pkv0, Wkv_dw, pkv, 128);
    conv1x1_k<<<g1, blk>>>(pspa1, 64, 0, Wq, 0, nullptr, ptmp, 64);
    dw3x3_k<<<gdw64, blk>>>(ptmp, Wq_dw, pq, 64);
    zero_k<<<10, 256>>>(pstats, 2560);
    gramnorm_k<<<ggram, blk>>>(pq, 64, pkv, 128, pG, pnq, pnk);
    softmax_meff_k<<<BSZ, 64>>>(temp, Wproj, pG, pnq, pnk, pmeff);
    conv1x1_k<<<g1, blk>>>(pkv, 128, 64, pmeff, 64 * 64, pspa1, pspa2, 64);

    // ===== fuse path =====
    // t1 = conv3x3(concat(fre2, spa2), Wf1) + bf1   (128 -> 64)
    conv3x3_k<128, false><<<g3, blk>>>(pfre2, pspa2, Wf1, bf1, ptmp, 64);
    // fuse = sigmoid(conv3x3(t1, Wf2) + bf2)        (64 -> 128)
    conv3x3_k<64, true><<<g3f2, blk>>>(ptmp, ptmp, Wf2, bf2, pkv0, 128);
    // res = fre2*fuse[:64] + spa2*fuse[64:], nan_to_num
    final_k<<<16384, 256>>>(pfre2, pspa2, pkv0, out);
}

// round 3
// speedup vs baseline: 1.0619x; 1.0001x over previous
#include <cuda_runtime.h>
#include <math.h>

// Problem constants (B=4, C=64, H=W=256)
#define BSZ 4
#define HDIM 256
#define WDIM 256
#define HW 65536

typedef unsigned long long ull;

// ---------------- scratch (device globals; no allocation allowed) ----------------
__device__ float g_fre1[(size_t)BSZ * 64 * HW];
__device__ float g_spa1[(size_t)BSZ * 64 * HW];
__device__ float g_tmp [(size_t)BSZ * 64 * HW];   // 1x1 q intermediate, later t1
__device__ float g_q   [(size_t)BSZ * 64 * HW];
__device__ float g_fre2[(size_t)BSZ * 64 * HW];
__device__ float g_spa2[(size_t)BSZ * 64 * HW];
__device__ float g_kv0 [(size_t)BSZ * 128 * HW];  // 1x1 kv intermediate, later fuse
__device__ float g_kv  [(size_t)BSZ * 128 * HW];
// stats: G[4][8][8][8] at 0, nq[4][64] at 2048, nk[4][64] at 2304
__device__ float g_stats[2560];
__device__ float g_Meff[BSZ * 64 * 64];

// ---------------- packed f32x2 helpers (FFMA2 — ptxas won't emit from C++) ----------------
__device__ __forceinline__ ull ffma2(ull a, ull b, ull c) {
    ull d;
    asm("fma.rn.f32x2 %0, %1, %2, %3;" : "=l"(d) : "l"(a), "l"(b), "l"(c));
    return d;
}
__device__ __forceinline__ ull packf2(float x, float y) {
    ull u; asm("mov.b64 %0, {%1, %2};" : "=l"(u) : "f"(x), "f"(y)); return u;
}
__device__ __forceinline__ float2 unpackf2(ull u) {
    float2 v; asm("mov.b64 {%0, %1}, %2;" : "=f"(v.x), "=f"(v.y) : "l"(u)); return v;
}

// ---------------- small utility kernels ----------------
__global__ void zero_k(float* p, int n) {
    int i = blockIdx.x * 256 + threadIdx.x;
    if (i < n) p[i] = 0.f;
}

__device__ __forceinline__ float fix_nan(float x) {
    return isfinite(x) ? x : 1e-5f;
}

// ---------------- conv 3x3, pad 1, optional bias / sigmoid, FFMA2 ----------------
// Block: 256 threads. Tile: 8 rows x 32 cols of output, 16 output channels.
// Input channels processed in pairs (packed float2); chunked by 16 through smem.
template <int CIN, bool SIG>
__global__ void __launch_bounds__(256)
conv3x3_k(const float* __restrict__ inA, const float* __restrict__ inB,
          const float* __restrict__ Wt, const float* __restrict__ bias,
          float* __restrict__ out, int coutTotal) {
    __shared__ float2 s_in[8][10][36];   // [ci2][row][col]; 36-col pad = 16B-aligned rows
    __shared__ float2 s_w[8][16][10];    // [ci2][co_local][tap(9, pad 10)]

    const int groups = coutTotal >> 4;
    const int b     = blockIdx.z / groups;
    const int cout0 = (blockIdx.z % groups) << 4;
    const int x0 = blockIdx.x * 32;
    const int y0 = blockIdx.y * 8;

    const int t   = threadIdx.x;
    const int pg  = t & 63;          // pixel group 0..63
    const int cg  = t >> 6;          // cout group 0..3
    const int row = pg >> 3;         // 0..7
    const int xl0 = (pg & 7) << 2;   // 0,4,...,28
    const int col0 = cg << 2;        // 0,4,8,12

    ull acc[4][4];
#pragma unroll
    for (int j = 0; j < 4; ++j)
#pragma unroll
        for (int p = 0; p < 4; ++p) acc[j][p] = 0ull;

    for (int ch0 = 0; ch0 < CIN; ch0 += 16) {
        // stage input tile (16 ch x 10 x 34), interleaved into channel pairs
        for (int i = t; i < 16 * 10 * 34; i += 256) {
            int ci  = i / 340;
            int rem = i - ci * 340;
            int r = rem / 34, c = rem - r * 34;
            int gy = y0 + r - 1, gx = x0 + c - 1;
            int cig = ch0 + ci;
            const float* src = (cig < 64) ? inA : inB;
            int ch = (cig < 64) ? cig : (cig - 64);
            float v = 0.f;
            if (gy >= 0 && gy < HDIM && gx >= 0 && gx < WDIM)
                v = src[((size_t)b * 64 + ch) * HW + gy * WDIM + gx];
            ((float*)&s_in[ci >> 1][r][c])[ci & 1] = v;
        }
        // stage weights as channel pairs: 8 ci2 x 16 co x 9 taps
        for (int i = t; i < 8 * 16 * 9; i += 256) {
            int tap = i % 9;
            int rest = i / 9;
            int col = rest & 15;
            int ci2 = rest >> 4;
            int cib = ch0 + ci2 * 2;
            float wx = Wt[((size_t)(cout0 + col) * CIN + cib) * 9 + tap];
            float wy = Wt[((size_t)(cout0 + col) * CIN + cib + 1) * 9 + tap];
            s_w[ci2][col][tap] = make_float2(wx, wy);
        }
        __syncthreads();

#pragma unroll
        for (int ci2 = 0; ci2 < 8; ++ci2) {
            ull v[3][6];
#pragma unroll
            for (int ky = 0; ky < 3; ++ky) {
                const ulonglong2* vp = (const ulonglong2*)&s_in[ci2][row + ky][xl0];
                ulonglong2 q0 = vp[0], q1 = vp[1], q2 = vp[2];
                v[ky][0] = q0.x; v[ky][1] = q0.y;
                v[ky][2] = q1.x; v[ky][3] = q1.y;
                v[ky][4] = q2.x; v[ky][5] = q2.y;
            }
#pragma unroll
            for (int j = 0; j < 4; ++j) {
                const ull* wr = (const ull*)&s_w[ci2][col0 + j][0];
                ull w[9];
#pragma unroll
                for (int tap = 0; tap < 9; ++tap) w[tap] = wr[tap];
#pragma unroll
                for (int ky = 0; ky < 3; ++ky)
#pragma unroll
                    for (int kx = 0; kx < 3; ++kx) {
#pragma unroll
                        for (int p = 0; p < 4; ++p)
                            acc[j][p] = ffma2(w[ky * 3 + kx], v[ky][p + kx], acc[j][p]);
                    }
            }
        }
        __syncthreads();
    }

#pragma unroll
    for (int j = 0; j < 4; ++j) {
        int co = cout0 + col0 + j;
        float bv = bias ? bias[co] : 0.f;
        float4 r;
        float2 a0 = unpackf2(acc[j][0]);
        float2 a1 = unpackf2(acc[j][1]);
        float2 a2 = unpackf2(acc[j][2]);
        float2 a3 = unpackf2(acc[j][3]);
        r.x = a0.x + a0.y + bv;
        r.y = a1.x + a1.y + bv;
        r.z = a2.x + a2.y + bv;
        r.w = a3.x + a3.y + bv;
        if (SIG) {
            r.x = 1.f / (1.f + expf(-r.x));
            r.y = 1.f / (1.f + expf(-r.y));
            r.z = 1.f / (1.f + expf(-r.z));
            r.w = 1.f / (1.f + expf(-r.w));
        }
        *(float4*)&out[((size_t)b * coutTotal + co) * HW + (size_t)(y0 + row) * WDIM + x0 + xl0] = r;
    }
}

// ---------------- conv 1x1 (per-pixel GEMM), cin=64, 64 couts per grid.y, FFMA2 ----------------
// Block: 256 threads. Thread = 4 pixels (2 packed pairs) x 8 couts.
// Weights staged duplicated (w,w) in smem. Per-batch weights (w_bs) + residual supported.
__global__ void __launch_bounds__(256)
conv1x1_k(const float* __restrict__ in, int in_cs, int in_off,
          const float* __restrict__ W, int w_bs,
          const float* __restrict__ resid,
          float* __restrict__ out, int out_cs) {
    __shared__ ull s_w[64 * 64];  // [ci][co_local] as (w,w)
    const int b   = blockIdx.z;
    const int co0 = blockIdx.y * 64;
    const int t   = threadIdx.x;
    const int pg  = t & 31;
    const int cg  = t >> 5;        // 0..7
    const int p   = blockIdx.x * 128 + pg * 4;

    const float* wb = W + (size_t)b * w_bs;
    for (int i = t; i < 64 * 64; i += 256) {
        int ci = i >> 6, col = i & 63;
        float w = wb[(size_t)(co0 + col) * 64 + ci];
        s_w[i] = packf2(w, w);
    }
    __syncthreads();

    ull acc[8][2];
#pragma unroll
    for (int j = 0; j < 8; ++j) { acc[j][0] = 0ull; acc[j][1] = 0ull; }

    const float* ip = in + ((size_t)b * in_cs + in_off) * HW + p;
#pragma unroll 4
    for (int ci = 0; ci < 64; ++ci) {
        ulonglong2 X = *(const ulonglong2*)(ip + (size_t)ci * HW);
        const ull* wr = &s_w[ci * 64 + cg * 8];
#pragma unroll
        for (int j = 0; j < 8; ++j) {
            acc[j][0] = ffma2(wr[j], X.x, acc[j][0]);
            acc[j][1] = ffma2(wr[j], X.y, acc[j][1]);
        }
    }

#pragma unroll
    for (int j = 0; j < 8; ++j) {
        int co = co0 + cg * 8 + j;
        size_t oidx = ((size_t)b * out_cs + co) * HW + p;
        float2 lo = unpackf2(acc[j][0]);
        float2 hi = unpackf2(acc[j][1]);
        float4 r = make_float4(lo.x, lo.y, hi.x, hi.y);
        if (resid) {
            float4 rv = *(const float4*)(resid + oidx);
            r.x += rv.x; r.y += rv.y; r.z += rv.z; r.w += rv.w;
        }
        *(float4*)(out + oidx) = r;
    }
}

// ---------------- depthwise 3x3, pad 1, no bias; 4 px/thread, hoisted predicates ----------------
// grid: (4, 16, B*C), block 256. Tile: 64 px wide x 16 rows.
__global__ void dw3x3_k(const float* __restrict__ in, const float* __restrict__ wt,
                        float* __restrict__ out, int C) {
    const int t = threadIdx.x;
    const int x0 = blockIdx.x * 64 + (t & 15) * 4;
    const int y  = blockIdx.y * 16 + (t >> 4);
    const int zc = blockIdx.z;       // b*C + c
    const int c = zc % C;
    const float* ip = in + (size_t)zc * HW;

    float w[9];
#pragma unroll
    for (int i = 0; i < 9; ++i) w[i] = __ldg(&wt[c * 9 + i]);

    float acc[4] = {0.f, 0.f, 0.f, 0.f};
    const bool hasL = (x0 > 0), hasR = (x0 < WDIM - 4);
#pragma unroll
    for (int ky = 0; ky < 3; ++ky) {
        int yy = y + ky - 1;
        if (yy < 0 || yy >= HDIM) continue;
        const float* rp = ip + yy * WDIM + x0;
        float4 m = *(const float4*)rp;
        float v[6];
        v[0] = hasL ? __ldg(rp - 1) : 0.f;
        v[1] = m.x; v[2] = m.y; v[3] = m.z; v[4] = m.w;
        v[5] = hasR ? __ldg(rp + 4) : 0.f;
#pragma unroll
        for (int kx = 0; kx < 3; ++kx)
#pragma unroll
            for (int p = 0; p < 4; ++p)
                acc[p] += w[ky * 3 + kx] * v[kx + p];
    }
    *(float4*)&out[(size_t)zc * HW + y * WDIM + x0] =
        make_float4(acc[0], acc[1], acc[2], acc[3]);
}

// ---------------- Gram matrix + channel norms, per (b, head) ----------------
// grid: (16 slices, 8 heads, 4 batch), block 256.
__global__ void gramnorm_k(const float* __restrict__ q, int qcs,
                           const float* __restrict__ k, int kcs,
                           float* __restrict__ G, float* __restrict__ nq,
                           float* __restrict__ nk) {
    const int b = blockIdx.z, h = blockIdx.y;
    const int p0 = blockIdx.x * 4096 + threadIdx.x;
    const float* qb = q + ((size_t)b * qcs + h * 8) * HW;
    const float* kb = k + ((size_t)b * kcs + h * 8) * HW;

    float acc[80];
#pragma unroll
    for (int i = 0; i < 80; ++i) acc[i] = 0.f;

    for (int it = 0; it < 16; ++it) {
        int p = p0 + it * 256;
        float qv[8], kv[8];
#pragma unroll
        for (int c = 0; c < 8; ++c) {
            qv[c] = qb[(size_t)c * HW + p];
            kv[c] = kb[(size_t)c * HW + p];
        }
#pragma unroll
        for (int c = 0; c < 8; ++c) {
            acc[64 + c] += qv[c] * qv[c];
            acc[72 + c] += kv[c] * kv[c];
#pragma unroll
            for (int d = 0; d < 8; ++d) acc[c * 8 + d] += qv[c] * kv[d];
        }
    }

    __shared__ float red[80][8];
    const int lane = threadIdx.x & 31, warp = threadIdx.x >> 5;
#pragma unroll
    for (int i = 0; i < 80; ++i) {
        float v = acc[i];
        v += __shfl_down_sync(0xffffffffu, v, 16);
        v += __shfl_down_sync(0xffffffffu, v, 8);
        v += __shfl_down_sync(0xffffffffu, v, 4);
        v += __shfl_down_sync(0xffffffffu, v, 2);
        v += __shfl_down_sync(0xffffffffu, v, 1);
        if (lane == 0) red[i][warp] = v;
    }
    __syncthreads();
    if (threadIdx.x < 80) {
        float s = 0.f;
#pragma unroll
        for (int w = 0; w < 8; ++w) s += red[threadIdx.x][w];
        int i = threadIdx.x;
        if (i < 64)
            atomicAdd(&G[(((size_t)b * 8 + h) * 8 + (i >> 3)) * 8 + (i & 7)], s);
        else if (i < 72)
            atomicAdd(&nq[b * 64 + h * 8 + (i - 64)], s);
        else
            atomicAdd(&nk[b * 64 + h * 8 + (i - 72)], s);
    }
}

// ---------------- softmax + fold proj: Meff[b] = Wproj @ blockdiag(attn) ----------------
__global__ void softmax_meff_k(const float* __restrict__ temp, const float* __restrict__ Wproj,
                               const float* __restrict__ G, const float* __restrict__ nq,
                               const float* __restrict__ nk, float* __restrict__ Meff) {
    const int b = blockIdx.x;
    const int t = threadIdx.x;   // 0..63
    __shared__ float attn[8][8][8];  // [head][c][d]
    {
        int h = t >> 3, c = t & 7;
        float nqc = fmaxf(sqrtf(nq[b * 64 + h * 8 + c]), 1e-12f);
        float row[8];
        float m = -1e30f;
#pragma unroll
        for (int d = 0; d < 8; ++d) {
            float nkd = fmaxf(sqrtf(nk[b * 64 + h * 8 + d]), 1e-12f);
            row[d] = temp[h] * G[(((size_t)b * 8 + h) * 8 + c) * 8 + d] / (nqc * nkd);
            m = fmaxf(m, row[d]);
        }
        float sum = 0.f;
#pragma unroll
        for (int d = 0; d < 8; ++d) { row[d] = expf(row[d] - m); sum += row[d]; }
        float inv = 1.f / sum;
#pragma unroll
        for (int d = 0; d < 8; ++d) attn[h][c][d] = row[d] * inv;
    }
    __syncthreads();
    const int o = t;
    for (int dg = 0; dg < 64; ++dg) {
        int hh = dg >> 3, j = dg & 7;
        float s = 0.f;
#pragma unroll
        for (int i = 0; i < 8; ++i) s += Wproj[o * 64 + hh * 8 + i] * attn[hh][i][j];
        Meff[((size_t)b * 64 + o) * 64 + dg] = s;
    }
}

// ---------------- final gate: res = fre2*fuse[:64] + spa2*fuse[64:], nan_to_num ----------------
__global__ void final_k(const float* __restrict__ f, const float* __restrict__ s,
                        const float* __restrict__ fuse, float* __restrict__ out) {
    size_t i4 = (size_t)blockIdx.x * 256 + threadIdx.x;
    size_t e = i4 * 4;
    int bc = (int)(e / HW);
    int p  = (int)(e % HW);
    int b = bc >> 6, c = bc & 63;
    float4 fv = *(const float4*)(f + e);
    float4 sv = *(const float4*)(s + e);
    float4 fa = *(const float4*)(fuse + ((size_t)(b * 128 + c)) * HW + p);
    float4 sa = *(const float4*)(fuse + ((size_t)(b * 128 + 64 + c)) * HW + p);
    float4 r;
    r.x = fix_nan(fv.x * fa.x + sv.x * sa.x);
    r.y = fix_nan(fv.y * fa.y + sv.y * sa.y);
    r.z = fix_nan(fv.z * fa.z + sv.z * sa.z);
    r.w = fix_nan(fv.w * fa.w + sv.w * sa.w);
    *(float4*)(out + e) = r;
}

// ---------------- host orchestration ----------------
extern "C" void kernel_launch(void* const* d_in, const int* in_sizes, int n_in,
                              void* d_out, int out_size) {
    const float* spa    = (const float*)d_in[0];
    const float* fre    = (const float*)d_in[1];
    const float* W_fre  = (const float*)d_in[2];
    const float* b_fre  = (const float*)d_in[3];
    const float* W_spa  = (const float*)d_in[4];
    const float* b_spa  = (const float*)d_in[5];
    const float* temp   = (const float*)d_in[6];
    const float* Wq     = (const float*)d_in[7];
    const float* Wq_dw  = (const float*)d_in[8];
    const float* Wkv    = (const float*)d_in[9];
    const float* Wkv_dw = (const float*)d_in[10];
    const float* Wproj  = (const float*)d_in[11];
    const float* Wf1    = (const float*)d_in[12];
    const float* bf1    = (const float*)d_in[13];
    const float* Wf2    = (const float*)d_in[14];
    const float* bf2    = (const float*)d_in[15];
    float* out = (float*)d_out;

    float *pfre1, *pspa1, *ptmp, *pq, *pfre2, *pspa2, *pkv0, *pkv, *pstats, *pmeff;
    cudaGetSymbolAddress((void**)&pfre1, g_fre1);
    cudaGetSymbolAddress((void**)&pspa1, g_spa1);
    cudaGetSymbolAddress((void**)&ptmp,  g_tmp);
    cudaGetSymbolAddress((void**)&pq,    g_q);
    cudaGetSymbolAddress((void**)&pfre2, g_fre2);
    cudaGetSymbolAddress((void**)&pspa2, g_spa2);
    cudaGetSymbolAddress((void**)&pkv0,  g_kv0);
    cudaGetSymbolAddress((void**)&pkv,   g_kv);
    cudaGetSymbolAddress((void**)&pstats, g_stats);
    cudaGetSymbolAddress((void**)&pmeff, g_Meff);
    float* pG  = pstats;
    float* pnq = pstats + 2048;
    float* pnk = pstats + 2304;

    const dim3 blk(256);
    const dim3 g3(8, 32, BSZ * 4);          // conv3x3 64->64
    const dim3 g3f2(8, 32, BSZ * 8);        // conv3x3 64->128
    const dim3 g1(512, 1, BSZ);             // conv1x1 64 couts
    const dim3 g1kv(512, 2, BSZ);           // conv1x1 128 couts
    const dim3 gdw64(4, 16, BSZ * 64);
    const dim3 gdw128(4, 16, BSZ * 128);
    const dim3 ggram(16, 8, BSZ);

    // 1) fre1 = conv3x3(fre, W_fre) + b_fre ; spa1 = conv3x3(spa, W_spa) + b_spa
    conv3x3_k<64, false><<<g3, blk>>>(fre, fre, W_fre, b_fre, pfre1, 64);
    conv3x3_k<64, false><<<g3, blk>>>(spa, spa, W_spa, b_spa, pspa1, 64);

    // ===== attention 1: q from fre1, kv from spa1, residual fre1 -> fre2 =====
    conv1x1_k<<<g1kv, blk>>>(pspa1, 64, 0, Wkv, 0, nullptr, pkv0, 128);
    dw3x3_k<<<gdw128, blk>>>(pkv0, Wkv_dw, pkv, 128);
    conv1x1_k<<<g1, blk>>>(pfre1, 64, 0, Wq, 0, nullptr, ptmp, 64);
    dw3x3_k<<<gdw64, blk>>>(ptmp, Wq_dw, pq, 64);
    zero_k<<<10, 256>>>(pstats, 2560);
    gramnorm_k<<<ggram, blk>>>(pq, 64, pkv, 128, pG, pnq, pnk);
    softmax_meff_k<<<BSZ, 64>>>(temp, Wproj, pG, pnq, pnk, pmeff);
    conv1x1_k<<<g1, blk>>>(pkv, 128, 64, pmeff, 64 * 64, pfre1, pfre2, 64);

    // ===== attention 2: q from spa1, kv from fre2, residual spa1 -> spa2 =====
    conv1x1_k<<<g1kv, blk>>>(pfre2, 64, 0, Wkv, 0, nullptr, pkv0, 128);
    dw3x3_k<<<gdw128, blk>>>(pkv0, Wkv_dw, pkv, 128);
    conv1x1_k<<<g1, blk>>>(pspa1, 64, 0, Wq, 0, nullptr, ptmp, 64);
    dw3x3_k<<<gdw64, blk>>>(ptmp, Wq_dw, pq, 64);
    zero_k<<<10, 256>>>(pstats, 2560);
    gramnorm_k<<<ggram, blk>>>(pq, 64, pkv, 128, pG, pnq, pnk);
    softmax_meff_k<<<BSZ, 64>>>(temp, Wproj, pG, pnq, pnk, pmeff);
    conv1x1_k<<<g1, blk>>>(pkv, 128, 64, pmeff, 64 * 64, pspa1, pspa2, 64);

    // ===== fuse path =====
    // t1 = conv3x3(concat(fre2, spa2), Wf1) + bf1   (128 -> 64)
    conv3x3_k<128, false><<<g3, blk>>>(pfre2, pspa2, Wf1, bf1, ptmp, 64);
    // fuse = sigmoid(conv3x3(t1, Wf2) + bf2)        (64 -> 128)
    conv3x3_k<64, true><<<g3f2, blk>>>(ptmp, ptmp, Wf2, bf2, pkv0, 128);
    // res = fre2*fuse[:64] + spa2*fuse[64:], nan_to_num
    final_k<<<16384, 256>>>(pfre2, pspa2, pkv0, out);
}